// round 16
// baseline (speedup 1.0000x reference)
#include <cuda_runtime.h>
#include <cuda_fp16.h>
#include <math.h>
#include <stdint.h>

#define TT 256
#define BB 256
#define II 256
#define HH 1024
#define BH (BB * HH)

// ----------------- scratch (device globals; no runtime allocation) -----------------
__device__ __half g_inp0[(size_t)TT * BB * HH];      // layer0 preact [T][B][H] fp16
__device__ __half g_inp1[(size_t)TT * BB * HH];      // layer1 preact [T][B][H] fp16
__device__ __half g_x[(size_t)TT * BB * II];         // x transposed [(t*B+b)][i] fp16
__device__ __half g_hist[(size_t)TT * BB * HH];      // layer0 h history fp16
__device__ __half g_w0h[HH * II];                    // W_ih0 hi fp16
__device__ __half g_w0l[HH * II];                    // W_ih0 lo fp16
__device__ __half g_h[2][BH];                        // layer1 h ping-pong fp16
__device__ unsigned g_arr[2 * 64];                   // barrier counters: [0]=rnn0, [64]=rnn1
__device__ unsigned g_done0[64 * 16];                // per-nt producer progress flags

// ----------------- portable (sm_80+) asm helpers ------------------------------------
__device__ __forceinline__ uint32_t smem_u32(const void* p) {
    uint32_t a;
    asm("{ .reg .u64 t; cvta.to.shared.u64 t, %1; cvt.u32.u64 %0, t; }" : "=r"(a) : "l"(p));
    return a;
}
__device__ __forceinline__ void cp16(uint32_t dst, const void* src) {
    asm volatile("cp.async.cg.shared.global [%0], [%1], 16;" :: "r"(dst), "l"(src));
}
#define CP_COMMIT() asm volatile("cp.async.commit_group;" ::: "memory")
#define CP_WAIT(n)  asm volatile("cp.async.wait_group %0;" :: "n"(n) : "memory")
#define BARG(id)    asm volatile("bar.sync %0, 128;" :: "r"(id) : "memory")

__device__ __forceinline__ void ldsm4(uint32_t* r, uint32_t a) {
    asm volatile("ldmatrix.sync.aligned.m8n8.x4.shared.b16 {%0,%1,%2,%3}, [%4];"
                 : "=r"(r[0]), "=r"(r[1]), "=r"(r[2]), "=r"(r[3]) : "r"(a));
}
__device__ __forceinline__ void mma16816(float* d, const uint32_t* a, uint32_t b0, uint32_t b1) {
    asm volatile(
        "mma.sync.aligned.m16n8k16.row.col.f32.f16.f16.f32 "
        "{%0,%1,%2,%3}, {%4,%5,%6,%7}, {%8,%9}, {%0,%1,%2,%3};"
        : "+f"(d[0]), "+f"(d[1]), "+f"(d[2]), "+f"(d[3])
        : "r"(a[0]), "r"(a[1]), "r"(a[2]), "r"(a[3]), "r"(b0), "r"(b1));
}

__device__ __forceinline__ uint32_t pack_h2(float a, float b) {
    __half2 h = __floats2half2_rn(a, b);
    return *(uint32_t*)&h;
}
__device__ __forceinline__ void split2h(float a, float b, uint32_t& hi, uint32_t& lo) {
    __half ah = __float2half_rn(a), bh = __float2half_rn(b);
    float ra = a - __half2float(ah), rb = b - __half2float(bh);
    hi = (uint32_t)__half_as_ushort(ah) | ((uint32_t)__half_as_ushort(bh) << 16);
    __half al = __float2half_rn(ra), bl = __float2half_rn(rb);
    lo = (uint32_t)__half_as_ushort(al) | ((uint32_t)__half_as_ushort(bl) << 16);
}

// L2-coherent vector load: REQUIRED for data produced in the SAME launch by
// other SMs (ld.global.nc/__ldg is undefined for intra-launch-written data).
__device__ __forceinline__ uint4 ldcg_u4(const void* p) {
    uint4 v;
    asm volatile("ld.global.cg.v4.u32 {%0,%1,%2,%3}, [%4];"
                 : "=r"(v.x), "=r"(v.y), "=r"(v.z), "=r"(v.w) : "l"(p));
    return v;
}

// ----------------- conversion kernels ------------------------------------------------
__global__ void __launch_bounds__(256) conv_x(const float* __restrict__ x) {
    int idx = blockIdx.x * 256 + threadIdx.x;      // one float4
    int i4  = idx & (II / 4 - 1);
    int rem = idx >> 6;                             // b*TT + t
    int t = rem & (TT - 1);
    int b = rem >> 8;
    float4 v = ((const float4*)x)[idx];
    uint32_t p0 = pack_h2(v.x, v.y);
    uint32_t p1 = pack_h2(v.z, v.w);
    *(uint2*)&g_x[((size_t)t * BB + b) * II + i4 * 4] = make_uint2(p0, p1);
}

__global__ void __launch_bounds__(256) conv_w0(const float* __restrict__ w, int n4) {
    int idx = blockIdx.x * 256 + threadIdx.x;
    if (idx >= n4) return;
    float4 v = ((const float4*)w)[idx];
    uint32_t h0, l0, h1, l1;
    split2h(v.x, v.y, h0, l0);
    split2h(v.z, v.w, h1, l1);
    *(uint2*)&g_w0h[(size_t)idx * 4] = make_uint2(h0, h1);
    *(uint2*)&g_w0l[(size_t)idx * 4] = make_uint2(l0, l1);
}

// ----------------- layer0 input GEMM: CTA 128m x 128n, K=256 -------------------------
#define G0_BUF 30720
#define G0_SMEM (3 * G0_BUF)

__global__ void __launch_bounds__(256) gemm0_f16(
    const float* __restrict__ bia, const float* __restrict__ bib)
{
    constexpr int KD = II;
    constexpr int NC = KD / 32;   // 8
    extern __shared__ char sm[];
    const uint32_t smb = smem_u32(sm);
    const int tid = threadIdx.x, wid = tid >> 5, l = tid & 31;
    const int m0 = blockIdx.y * 128, n0 = blockIdx.x * 128;
    const int wm = (wid >> 1) * 32, wn = (wid & 1) * 64;

    const int ar = tid >> 1, ahalf = tid & 1;
    const __half* gA  = g_x   + (size_t)(m0 + ar) * KD + ahalf * 16;
    const __half* gWh = g_w0h + (size_t)(n0 + ar) * KD + ahalf * 16;
    const __half* gWl = g_w0l + (size_t)(n0 + ar) * KD + ahalf * 16;
    const uint32_t dA  = smb + (uint32_t)ar * 80 + ahalf * 32;
    const uint32_t dBh = dA + 10240;
    const uint32_t dBl = dA + 20480;

    float acc[2][8][4];
#pragma unroll
    for (int a = 0; a < 2; a++)
#pragma unroll
        for (int b = 0; b < 8; b++)
#pragma unroll
            for (int c = 0; c < 4; c++) acc[a][b][c] = 0.f;

    const uint32_t aFragOff = (uint32_t)(wm + (l & 15)) * 80 + (l >> 4) * 16;
    const int nloc = wn + (l & 7) + ((l >> 4) << 3);
    const uint32_t bFragOff = (uint32_t)nloc * 80 + ((l >> 3) & 1) * 16;

#define G0_STAGE(kc, s) do { \
        uint32_t o = (uint32_t)(s) * G0_BUF; \
        const __half* pA = gA + (kc) * 32; \
        const __half* pH = gWh + (kc) * 32; \
        const __half* pL = gWl + (kc) * 32; \
        cp16(dA + o, pA);        cp16(dA + o + 16, pA + 8); \
        cp16(dBh + o, pH);       cp16(dBh + o + 16, pH + 8); \
        cp16(dBl + o, pL);       cp16(dBl + o + 16, pL + 8); \
        CP_COMMIT(); \
    } while (0)

    G0_STAGE(0, 0);
    G0_STAGE(1, 1);

    for (int kc = 0; kc < NC; ++kc) {
        if (kc < NC - 1) { CP_WAIT(1); } else { CP_WAIT(0); }
        __syncthreads();
        if (kc + 2 < NC) G0_STAGE(kc + 2, (kc + 2) % 3);
        const uint32_t base = smb + (uint32_t)(kc % 3) * G0_BUF;
#pragma unroll
        for (int kk = 0; kk < 2; ++kk) {
            uint32_t a[2][4];
#pragma unroll
            for (int mc = 0; mc < 2; ++mc)
                ldsm4(a[mc], base + aFragOff + mc * 1280 + kk * 32);
            uint32_t bh[4][4];
#pragma unroll
            for (int nc = 0; nc < 4; ++nc)
                ldsm4(bh[nc], base + 10240 + bFragOff + nc * 1280 + kk * 32);
#pragma unroll
            for (int mc = 0; mc < 2; ++mc)
#pragma unroll
                for (int nc = 0; nc < 4; ++nc) {
                    mma16816(acc[mc][nc * 2 + 0], a[mc], bh[nc][0], bh[nc][1]);
                    mma16816(acc[mc][nc * 2 + 1], a[mc], bh[nc][2], bh[nc][3]);
                }
            uint32_t bl[4][4];
#pragma unroll
            for (int nc = 0; nc < 4; ++nc)
                ldsm4(bl[nc], base + 20480 + bFragOff + nc * 1280 + kk * 32);
#pragma unroll
            for (int mc = 0; mc < 2; ++mc)
#pragma unroll
                for (int nc = 0; nc < 4; ++nc) {
                    mma16816(acc[mc][nc * 2 + 0], a[mc], bl[nc][0], bl[nc][1]);
                    mma16816(acc[mc][nc * 2 + 1], a[mc], bl[nc][2], bl[nc][3]);
                }
        }
    }

#pragma unroll
    for (int mc = 0; mc < 2; ++mc) {
        int r0 = m0 + wm + mc * 16 + (l >> 2);
#pragma unroll
        for (int f = 0; f < 8; ++f) {
            int c = n0 + wn + f * 8 + (l & 3) * 2;
            float bs0 = bia[c] + bib[c];
            float bs1 = bia[c + 1] + bib[c + 1];
            *(uint32_t*)&g_inp0[(size_t)r0 * HH + c] =
                pack_h2(acc[mc][f][0] + bs0, acc[mc][f][1] + bs1);
            *(uint32_t*)&g_inp0[(size_t)(r0 + 8) * HH + c] =
                pack_h2(acc[mc][f][2] + bs0, acc[mc][f][3] + bs1);
        }
    }
#undef G0_STAGE
}

// ----------------- CONCURRENT two-layer recurrence -----------------------------------
// 128 CTAs: blocks 0..63 = layer0 (rec + inp1 projection), 64..127 = layer1 (trails
// layer0 via per-nt flags). Each CTA: m = all 256 batch rows, n-tile 16.
// 16 warps = 4 K-groups x 4 warps; warp tile 64m x 16n (4 m-frags).
#define RB_W0H  0
#define RB_W0L  33024
#define RB_WI   66048
#define RB_A0   99072
#define RB_A1   66048
#define RB_ABUF 12288
#define RB_SMEM 197376

__global__ void __launch_bounds__(512, 1) rnn_both(
    const float* __restrict__ Whh0, const float* __restrict__ Wih1,
    const float* __restrict__ bi1,  const float* __restrict__ bh1,
    const float* __restrict__ Whh1)
{
    extern __shared__ char sm[];
    const uint32_t smb = smem_u32(sm);
    const int tid = threadIdx.x, wid = tid >> 5, l = tid & 31;
    const int g = wid >> 2;            // K-group 0..3
    const int w4 = wid & 3;            // 4 m-quarters (64 rows each)
    const int wm = w4 * 64;
    const int role = blockIdx.x >> 6;  // 0 = layer0, 1 = layer1
    const int nt = blockIdx.x & 63;
    const int n0 = nt * 16;

    const uint32_t aFragOff = (uint32_t)(wm + (l & 15)) * 48 + (uint32_t)(l >> 4) * 16;
    const int nloc = (l & 7) + ((l >> 4) << 3);
    const uint32_t bSel = (uint32_t)((l >> 3) & 1) * 16;
    const int gt = tid & 127;
    const int r0s = gt * 2;
    const int erow = tid >> 1;
    const int ecol = (tid & 1) * 8;
    const int gbar = 1 + g;

    if (role == 0) {
        // ---------------- layer0: rec (2-term Whh0) + projection (Wih1) -------------
        for (int i = tid; i < 4096; i += 512) {
            int n = i >> 8, k = (i & 255) * 4;
            uint32_t off = (uint32_t)n * 2064 + (uint32_t)k * 2;
            float4 wv = *(const float4*)&Whh0[(size_t)(n0 + n) * HH + k];
            uint32_t h0, l0, h1, l1;
            split2h(wv.x, wv.y, h0, l0);
            split2h(wv.z, wv.w, h1, l1);
            *(uint2*)(sm + RB_W0H + off) = make_uint2(h0, h1);
            *(uint2*)(sm + RB_W0L + off) = make_uint2(l0, l1);
            float4 iv = *(const float4*)&Wih1[(size_t)(n0 + n) * HH + k];
            *(uint2*)(sm + RB_WI + off) =
                make_uint2(pack_h2(iv.x, iv.y), pack_h2(iv.z, iv.w));
        }
        __syncthreads();

        const uint32_t bH = smb + RB_W0H + (uint32_t)nloc * 2064 + bSel;
        const uint32_t bL = smb + RB_W0L + (uint32_t)nloc * 2064 + bSel;
        const uint32_t bI = smb + RB_WI  + (uint32_t)nloc * 2064 + bSel;
        const uint32_t sdst0 = smb + RB_A0 + (uint32_t)g * (2 * RB_ABUF)
                             + (uint32_t)r0s * 48;
        const uint32_t psBase = smb + RB_A0;

        float pb[8];
#pragma unroll
        for (int j = 0; j < 8; j++)
            pb[j] = __ldg(&bi1[n0 + ecol + j]) + __ldg(&bh1[n0 + ecol + j]);

        unsigned* const bctr = &g_arr[0];
        unsigned* const flag = &g_done0[nt * 16];

        for (int t = 0; t <= TT; ++t) {
            const bool hasRec = (t < TT);
            uint4 piu = make_uint4(0u, 0u, 0u, 0u);
            if (hasRec) {
                // inp0 written by a previous kernel launch -> __ldg safe
                const __half* ip = g_inp0 + (size_t)t * BH
                                 + (size_t)erow * HH + n0 + ecol;
                piu = __ldg((const uint4*)ip);
            }

            float accr[4][2][4], accp[4][2][4];
            if (t > 0) {
#pragma unroll
                for (int a = 0; a < 4; a++)
#pragma unroll
                    for (int b = 0; b < 2; b++)
#pragma unroll
                        for (int c2 = 0; c2 < 4; c2++) {
                            accr[a][b][c2] = 0.f; accp[a][b][c2] = 0.f;
                        }

                const __half* gsrc = g_hist + (size_t)(t - 1) * BH
                                   + (size_t)r0s * HH + g * 256;
#define R0_STAGE(c, buf) do { \
                    const __half* p = gsrc + (c) * 16; \
                    uint32_t d = sdst0 + (uint32_t)(buf) * RB_ABUF; \
                    cp16(d, p);        cp16(d + 16, p + 8); \
                    cp16(d + 48, p + HH); cp16(d + 64, p + HH + 8); \
                    CP_COMMIT(); \
                } while (0)

                R0_STAGE(0, 0);

                for (int c = 0; c < 16; ++c) {
                    CP_WAIT(0);
                    BARG(gbar);
                    if (c < 15) R0_STAGE(c + 1, (c + 1) & 1);
                    const uint32_t abase = smb + RB_A0
                        + (uint32_t)g * (2 * RB_ABUF) + (uint32_t)(c & 1) * RB_ABUF;
                    const uint32_t kb = (uint32_t)(g * 256 + c * 16) * 2;
                    uint32_t bhv[4], blv[4], biv[4];
                    ldsm4(biv, bI + kb);
                    if (hasRec) { ldsm4(bhv, bH + kb); ldsm4(blv, bL + kb); }
#pragma unroll
                    for (int mf = 0; mf < 4; ++mf) {
                        uint32_t a0[4];
                        ldsm4(a0, abase + aFragOff + mf * 768);
                        if (hasRec) {
                            mma16816(accr[mf][0], a0, bhv[0], bhv[1]);
                            mma16816(accr[mf][1], a0, bhv[2], bhv[3]);
                            mma16816(accr[mf][0], a0, blv[0], blv[1]);
                            mma16816(accr[mf][1], a0, blv[2], blv[3]);
                        }
                        mma16816(accp[mf][0], a0, biv[0], biv[1]);
                        mma16816(accp[mf][1], a0, biv[2], biv[3]);
                    }
                }
#undef R0_STAGE

                __syncthreads();   // all chunks consumed; A region free
                if (hasRec) {
#pragma unroll
                    for (int mf = 0; mf < 4; ++mf)
#pragma unroll
                        for (int nf = 0; nf < 2; ++nf) {
                            int r = wm + mf * 16 + (l >> 2);
                            int cc = nf * 8 + (l & 3) * 2;
                            uint32_t pa = psBase + (uint32_t)g * 16384
                                        + (uint32_t)r * 64 + cc * 4;
                            asm volatile("st.shared.v2.f32 [%0], {%1, %2};"
                                :: "r"(pa), "f"(accr[mf][nf][0]), "f"(accr[mf][nf][1]));
                            asm volatile("st.shared.v2.f32 [%0], {%1, %2};"
                                :: "r"(pa + 512), "f"(accr[mf][nf][2]), "f"(accr[mf][nf][3]));
                        }
                }
                __syncthreads();
            }

            // --- rec epilogue: h0[t] = tanh(partials + inp0[t]); ARRIVE --------------
            unsigned bar_tgt = 0;
            if (hasRec) {
                float v[8];
                {
                    const __half2* ph = (const __half2*)&piu;
#pragma unroll
                    for (int j = 0; j < 4; j++) {
                        float2 f = __half22float2(ph[j]);
                        v[2 * j] = f.x; v[2 * j + 1] = f.y;
                    }
                }
                if (t > 0) {
                    const uint32_t pa = psBase + (uint32_t)erow * 64 + ecol * 4;
#pragma unroll
                    for (int gg = 0; gg < 4; ++gg) {
                        float4 q0, q1;
                        asm volatile("ld.shared.v4.f32 {%0,%1,%2,%3}, [%4];"
                                     : "=f"(q0.x), "=f"(q0.y), "=f"(q0.z), "=f"(q0.w)
                                     : "r"(pa + gg * 16384));
                        asm volatile("ld.shared.v4.f32 {%0,%1,%2,%3}, [%4];"
                                     : "=f"(q1.x), "=f"(q1.y), "=f"(q1.z), "=f"(q1.w)
                                     : "r"(pa + gg * 16384 + 16));
                        v[0] += q0.x; v[1] += q0.y; v[2] += q0.z; v[3] += q0.w;
                        v[4] += q1.x; v[5] += q1.y; v[6] += q1.z; v[7] += q1.w;
                    }
                }
#pragma unroll
                for (int j = 0; j < 8; j++) v[j] = tanhf(v[j]);
                uint4 u;
                u.x = pack_h2(v[0], v[1]); u.y = pack_h2(v[2], v[3]);
                u.z = pack_h2(v[4], v[5]); u.w = pack_h2(v[6], v[7]);
                *(uint4*)&g_hist[(size_t)t * BH + (size_t)erow * HH + n0 + ecol] = u;

                __syncthreads();
                if (tid == 0) {
                    __threadfence();
                    unsigned a = atomicAdd(bctr, 1u) + 1u;
                    bar_tgt = ((a - 1u) / 64u + 1u) * 64u;
                }
            }

            // --- phase B (overlapped): inp1[t-1] = proj + bias; signal rnn1 ----------
            if (t > 0) {
#pragma unroll
                for (int mf = 0; mf < 4; ++mf)
#pragma unroll
                    for (int nf = 0; nf < 2; ++nf) {
                        int r = wm + mf * 16 + (l >> 2);
                        int cc = nf * 8 + (l & 3) * 2;
                        uint32_t pa = psBase + (uint32_t)g * 16384
                                    + (uint32_t)r * 64 + cc * 4;
                        asm volatile("st.shared.v2.f32 [%0], {%1, %2};"
                            :: "r"(pa), "f"(accp[mf][nf][0]), "f"(accp[mf][nf][1]));
                        asm volatile("st.shared.v2.f32 [%0], {%1, %2};"
                            :: "r"(pa + 512), "f"(accp[mf][nf][2]), "f"(accp[mf][nf][3]));
                    }
                __syncthreads();
                {
                    float v[8] = { pb[0], pb[1], pb[2], pb[3],
                                   pb[4], pb[5], pb[6], pb[7] };
                    const uint32_t pa = psBase + (uint32_t)erow * 64 + ecol * 4;
#pragma unroll
                    for (int gg = 0; gg < 4; ++gg) {
                        float4 q0, q1;
                        asm volatile("ld.shared.v4.f32 {%0,%1,%2,%3}, [%4];"
                                     : "=f"(q0.x), "=f"(q0.y), "=f"(q0.z), "=f"(q0.w)
                                     : "r"(pa + gg * 16384));
                        asm volatile("ld.shared.v4.f32 {%0,%1,%2,%3}, [%4];"
                                     : "=f"(q1.x), "=f"(q1.y), "=f"(q1.z), "=f"(q1.w)
                                     : "r"(pa + gg * 16384 + 16));
                        v[0] += q0.x; v[1] += q0.y; v[2] += q0.z; v[3] += q0.w;
                        v[4] += q1.x; v[5] += q1.y; v[6] += q1.z; v[7] += q1.w;
                    }
                    uint4 u;
                    u.x = pack_h2(v[0], v[1]); u.y = pack_h2(v[2], v[3]);
                    u.z = pack_h2(v[4], v[5]); u.w = pack_h2(v[6], v[7]);
                    *(uint4*)&g_inp1[(size_t)(t - 1) * BH
                                   + (size_t)erow * HH + n0 + ecol] = u;
                }
                __syncthreads();   // all inp1 writes before flag
                if (tid == 0) {
                    __threadfence();
                    atomicExch(flag, (unsigned)t);   // inp1[0..t-1] ready
                }
            }

            // --- wait side of own barrier -------------------------------------------
            if (hasRec) {
                if (tid == 0) {
                    while (*((volatile unsigned*)bctr) < bar_tgt) { }
                    __threadfence();
                }
                __syncthreads();
            }
        }
    } else {
        // ---------------- layer1: rec (2-term Whh1), trails layer0 ------------------
        for (int i = tid; i < 4096; i += 512) {
            int n = i >> 8, k = (i & 255) * 4;
            uint32_t off = (uint32_t)n * 2064 + (uint32_t)k * 2;
            float4 wv = *(const float4*)&Whh1[(size_t)(n0 + n) * HH + k];
            uint32_t h0, l0, h1, l1;
            split2h(wv.x, wv.y, h0, l0);
            split2h(wv.z, wv.w, h1, l1);
            *(uint2*)(sm + RB_W0H + off) = make_uint2(h0, h1);   // W1h at 0
            *(uint2*)(sm + RB_W0L + off) = make_uint2(l0, l1);   // W1l at 33024
        }
        __syncthreads();

        const uint32_t bH = smb + RB_W0H + (uint32_t)nloc * 2064 + bSel;
        const uint32_t bL = smb + RB_W0L + (uint32_t)nloc * 2064 + bSel;
        const uint32_t sdst0 = smb + RB_A1 + (uint32_t)g * (2 * RB_ABUF)
                             + (uint32_t)r0s * 48;
        const uint32_t psBase = smb + RB_A1;

        unsigned* const bctr = &g_arr[64];
        unsigned* const flag = &g_done0[nt * 16];

        for (int t = 0; t < TT; ++t) {
            // wait for producer: inp1[t] ready when flag >= t+1
            if (tid == 0) {
                while (*((volatile unsigned*)flag) < (unsigned)(t + 1)) { }
                __threadfence();
            }
            __syncthreads();

            // inp1 is produced IN THIS LAUNCH by other SMs -> MUST use L2-coherent load
            const __half* ip = g_inp1 + (size_t)t * BH
                             + (size_t)erow * HH + n0 + ecol;
            uint4 piu = ldcg_u4(ip);

            float acc[4][2][4];
            if (t > 0) {
#pragma unroll
                for (int a = 0; a < 4; a++)
#pragma unroll
                    for (int b = 0; b < 2; b++)
#pragma unroll
                        for (int c2 = 0; c2 < 4; c2++) acc[a][b][c2] = 0.f;

                const __half* gsrc = g_h[1 - (t & 1)]
                                   + (size_t)r0s * HH + g * 256;
#define R1_STAGE(c, buf) do { \
                    const __half* p = gsrc + (c) * 16; \
                    uint32_t d = sdst0 + (uint32_t)(buf) * RB_ABUF; \
                    cp16(d, p);        cp16(d + 16, p + 8); \
                    cp16(d + 48, p + HH); cp16(d + 64, p + HH + 8); \
                    CP_COMMIT(); \
                } while (0)

                R1_STAGE(0, 0);

                for (int c = 0; c < 16; ++c) {
                    CP_WAIT(0);
                    BARG(gbar);
                    if (c < 15) R1_STAGE(c + 1, (c + 1) & 1);
                    const uint32_t abase = smb + RB_A1
                        + (uint32_t)g * (2 * RB_ABUF) + (uint32_t)(c & 1) * RB_ABUF;
                    const uint32_t kb = (uint32_t)(g * 256 + c * 16) * 2;
                    uint32_t bhv[4], blv[4];
                    ldsm4(bhv, bH + kb);
                    ldsm4(blv, bL + kb);
#pragma unroll
                    for (int mf = 0; mf < 4; ++mf) {
                        uint32_t a0[4];
                        ldsm4(a0, abase + aFragOff + mf * 768);
                        mma16816(acc[mf][0], a0, bhv[0], bhv[1]);
                        mma16816(acc[mf][1], a0, bhv[2], bhv[3]);
                        mma16816(acc[mf][0], a0, blv[0], blv[1]);
                        mma16816(acc[mf][1], a0, blv[2], blv[3]);
                    }
                }
#undef R1_STAGE

                __syncthreads();
#pragma unroll
                for (int mf = 0; mf < 4; ++mf)
#pragma unroll
                    for (int nf = 0; nf < 2; ++nf) {
                        int r = wm + mf * 16 + (l >> 2);
                        int cc = nf * 8 + (l & 3) * 2;
                        uint32_t pa = psBase + (uint32_t)g * 16384
                                    + (uint32_t)r * 64 + cc * 4;
                        asm volatile("st.shared.v2.f32 [%0], {%1, %2};"
                            :: "r"(pa), "f"(acc[mf][nf][0]), "f"(acc[mf][nf][1]));
                        asm volatile("st.shared.v2.f32 [%0], {%1, %2};"
                            :: "r"(pa + 512), "f"(acc[mf][nf][2]), "f"(acc[mf][nf][3]));
                    }
                __syncthreads();
            }

            {
                float v[8];
                {
                    const __half2* ph = (const __half2*)&piu;
#pragma unroll
                    for (int j = 0; j < 4; j++) {
                        float2 f = __half22float2(ph[j]);
                        v[2 * j] = f.x; v[2 * j + 1] = f.y;
                    }
                }
                if (t > 0) {
                    const uint32_t pa = psBase + (uint32_t)erow * 64 + ecol * 4;
#pragma unroll
                    for (int gg = 0; gg < 4; ++gg) {
                        float4 q0, q1;
                        asm volatile("ld.shared.v4.f32 {%0,%1,%2,%3}, [%4];"
                                     : "=f"(q0.x), "=f"(q0.y), "=f"(q0.z), "=f"(q0.w)
                                     : "r"(pa + gg * 16384));
                        asm volatile("ld.shared.v4.f32 {%0,%1,%2,%3}, [%4];"
                                     : "=f"(q1.x), "=f"(q1.y), "=f"(q1.z), "=f"(q1.w)
                                     : "r"(pa + gg * 16384 + 16));
                        v[0] += q0.x; v[1] += q0.y; v[2] += q0.z; v[3] += q0.w;
                        v[4] += q1.x; v[5] += q1.y; v[6] += q1.z; v[7] += q1.w;
                    }
                }
#pragma unroll
                for (int j = 0; j < 8; j++) v[j] = tanhf(v[j]);
                uint4 u;
                u.x = pack_h2(v[0], v[1]); u.y = pack_h2(v[2], v[3]);
                u.z = pack_h2(v[4], v[5]); u.w = pack_h2(v[6], v[7]);
                *(uint4*)&g_h[t & 1][(size_t)erow * HH + n0 + ecol] = u;
            }

            // own 64-CTA barrier
            __syncthreads();
            if (tid == 0) {
                __threadfence();
                unsigned a = atomicAdd(bctr, 1u) + 1u;
                unsigned tgt = ((a - 1u) / 64u + 1u) * 64u;
                while (*((volatile unsigned*)bctr) < tgt) { }
                __threadfence();
            }
            __syncthreads();
        }

        // reset partner flag for next launch (producer provably done: flag hit 256)
        if (tid == 0) atomicExch(flag, 0u);
    }
}

// ----------------- final FC + ReLU ---------------------------------------------------
__global__ void __launch_bounds__(256) fc_kernel(
    const float* __restrict__ fcW, const float* __restrict__ fcb,
    float* __restrict__ out)
{
    const int b = blockIdx.x;
    const int tid = threadIdx.x;
    const __half* h = &g_h[1][(size_t)b * HH];   // t=255 -> buffer 1
    float s = 0.f;
    for (int i = tid; i < HH; i += 256) s += __half2float(h[i]) * fcW[i];
#pragma unroll
    for (int o = 16; o; o >>= 1) s += __shfl_xor_sync(0xFFFFFFFFu, s, o);
    __shared__ float red[8];
    if ((tid & 31) == 0) red[tid >> 5] = s;
    __syncthreads();
    if (tid == 0) {
        float tot = 0.f;
#pragma unroll
        for (int i = 0; i < 8; i++) tot += red[i];
        out[b] = fmaxf(tot + fcb[0], 0.f);
    }
}

// ----------------- launch ------------------------------------------------------------
extern "C" void kernel_launch(void* const* d_in, const int* in_sizes, int n_in,
                              void* d_out, int out_size)
{
    const float* x     = (const float*)d_in[0];
    const float* W_ih0 = (const float*)d_in[1];
    const float* W_hh0 = (const float*)d_in[2];
    const float* b_ih0 = (const float*)d_in[3];
    const float* b_hh0 = (const float*)d_in[4];
    const float* W_ih1 = (const float*)d_in[5];
    const float* W_hh1 = (const float*)d_in[6];
    const float* b_ih1 = (const float*)d_in[7];
    const float* b_hh1 = (const float*)d_in[8];
    const float* fc_W  = (const float*)d_in[9];
    const float* fc_b  = (const float*)d_in[10];
    float* out = (float*)d_out;

    cudaFuncSetAttribute(gemm0_f16, cudaFuncAttributeMaxDynamicSharedMemorySize, G0_SMEM);
    cudaFuncSetAttribute(rnn_both, cudaFuncAttributeMaxDynamicSharedMemorySize, RB_SMEM);

    conv_x<<<(TT * BB * II / 4) / 256, 256>>>(x);
    conv_w0<<<(HH * II / 4 + 255) / 256, 256>>>(W_ih0, HH * II / 4);

    dim3 g0grid(HH / 128, (TT * BB) / 128);  // (8, 512)
    gemm0_f16<<<g0grid, 256, G0_SMEM>>>(b_ih0, b_hh0);
    rnn_both<<<128, 512, RB_SMEM>>>(W_hh0, W_ih1, b_ih1, b_hh1, W_hh1);
    fc_kernel<<<BB, 256>>>(fc_W, fc_b, out);
}

// round 17
// speedup vs baseline: 1.5476x; 1.5476x over previous
#include <cuda_runtime.h>
#include <cuda_fp16.h>
#include <math.h>
#include <stdint.h>

#define TT 256
#define BB 256
#define II 256
#define HH 1024
#define BH (BB * HH)

// ----------------- scratch (device globals; no runtime allocation) -----------------
__device__ __half g_inp0[(size_t)TT * BB * HH];      // layer0 preact [T][B][H] fp16
__device__ __half g_inp1[(size_t)TT * BB * HH];      // layer1 preact [T][B][H] fp16
__device__ __half g_x[(size_t)TT * BB * II];         // x transposed [(t*B+b)][i] fp16
__device__ __half g_hist[(size_t)TT * BB * HH];      // layer0 h history fp16
__device__ __half g_w0h[HH * II];                    // W_ih0 hi fp16
__device__ __half g_w0l[HH * II];                    // W_ih0 lo fp16
__device__ __half g_h[2][BH];                        // layer1 h ping-pong fp16
__device__ unsigned g_arr[4 * 64];                   // per-mt-group barrier counters

// ----------------- mt-group barrier (32 CTAs per group) -----------------------------
__device__ __forceinline__ void group_barrier(int mt) {
    __syncthreads();
    if (threadIdx.x == 0) {
        __threadfence();
        unsigned* ctr = &g_arr[mt * 64];
        unsigned a = atomicAdd(ctr, 1u) + 1u;
        unsigned target = ((a - 1u) / 32u + 1u) * 32u;
        while (*((volatile unsigned*)ctr) < target) { }
        __threadfence();
    }
    __syncthreads();
}

// ----------------- portable (sm_80+) asm helpers ------------------------------------
__device__ __forceinline__ uint32_t smem_u32(const void* p) {
    uint32_t a;
    asm("{ .reg .u64 t; cvta.to.shared.u64 t, %1; cvt.u32.u64 %0, t; }" : "=r"(a) : "l"(p));
    return a;
}
__device__ __forceinline__ void cp16(uint32_t dst, const void* src) {
    asm volatile("cp.async.cg.shared.global [%0], [%1], 16;" :: "r"(dst), "l"(src));
}
#define CP_COMMIT() asm volatile("cp.async.commit_group;" ::: "memory")
#define CP_WAIT(n)  asm volatile("cp.async.wait_group %0;" :: "n"(n) : "memory")
#define BARG(id)    asm volatile("bar.sync %0, 128;" :: "r"(id) : "memory")

__device__ __forceinline__ void ldsm4(uint32_t* r, uint32_t a) {
    asm volatile("ldmatrix.sync.aligned.m8n8.x4.shared.b16 {%0,%1,%2,%3}, [%4];"
                 : "=r"(r[0]), "=r"(r[1]), "=r"(r[2]), "=r"(r[3]) : "r"(a));
}
__device__ __forceinline__ void mma16816(float* d, const uint32_t* a, uint32_t b0, uint32_t b1) {
    asm volatile(
        "mma.sync.aligned.m16n8k16.row.col.f32.f16.f16.f32 "
        "{%0,%1,%2,%3}, {%4,%5,%6,%7}, {%8,%9}, {%0,%1,%2,%3};"
        : "+f"(d[0]), "+f"(d[1]), "+f"(d[2]), "+f"(d[3])
        : "r"(a[0]), "r"(a[1]), "r"(a[2]), "r"(a[3]), "r"(b0), "r"(b1));
}

__device__ __forceinline__ uint32_t pack_h2(float a, float b) {
    __half2 h = __floats2half2_rn(a, b);
    return *(uint32_t*)&h;
}
__device__ __forceinline__ void split2h(float a, float b, uint32_t& hi, uint32_t& lo) {
    __half ah = __float2half_rn(a), bh = __float2half_rn(b);
    float ra = a - __half2float(ah), rb = b - __half2float(bh);
    hi = (uint32_t)__half_as_ushort(ah) | ((uint32_t)__half_as_ushort(bh) << 16);
    __half al = __float2half_rn(ra), bl = __float2half_rn(rb);
    lo = (uint32_t)__half_as_ushort(al) | ((uint32_t)__half_as_ushort(bl) << 16);
}

// ----------------- conversion kernels ------------------------------------------------
__global__ void __launch_bounds__(256) conv_x(const float* __restrict__ x) {
    int idx = blockIdx.x * 256 + threadIdx.x;      // one float4
    int i4  = idx & (II / 4 - 1);
    int rem = idx >> 6;                             // b*TT + t
    int t = rem & (TT - 1);
    int b = rem >> 8;
    float4 v = ((const float4*)x)[idx];
    uint32_t p0 = pack_h2(v.x, v.y);
    uint32_t p1 = pack_h2(v.z, v.w);
    *(uint2*)&g_x[((size_t)t * BB + b) * II + i4 * 4] = make_uint2(p0, p1);
}

__global__ void __launch_bounds__(256) conv_w0(const float* __restrict__ w, int n4) {
    int idx = blockIdx.x * 256 + threadIdx.x;
    if (idx >= n4) return;
    float4 v = ((const float4*)w)[idx];
    uint32_t h0, l0, h1, l1;
    split2h(v.x, v.y, h0, l0);
    split2h(v.z, v.w, h1, l1);
    *(uint2*)&g_w0h[(size_t)idx * 4] = make_uint2(h0, h1);
    *(uint2*)&g_w0l[(size_t)idx * 4] = make_uint2(l0, l1);
}

// ----------------- layer0 input GEMM: CTA 128m x 128n, K=256 -------------------------
#define G0_BUF 30720
#define G0_SMEM (3 * G0_BUF)

__global__ void __launch_bounds__(256) gemm0_f16(
    const float* __restrict__ bia, const float* __restrict__ bib)
{
    constexpr int KD = II;
    constexpr int NC = KD / 32;   // 8
    extern __shared__ char sm[];
    const uint32_t smb = smem_u32(sm);
    const int tid = threadIdx.x, wid = tid >> 5, l = tid & 31;
    const int m0 = blockIdx.y * 128, n0 = blockIdx.x * 128;
    const int wm = (wid >> 1) * 32, wn = (wid & 1) * 64;

    const int ar = tid >> 1, ahalf = tid & 1;
    const __half* gA  = g_x   + (size_t)(m0 + ar) * KD + ahalf * 16;
    const __half* gWh = g_w0h + (size_t)(n0 + ar) * KD + ahalf * 16;
    const __half* gWl = g_w0l + (size_t)(n0 + ar) * KD + ahalf * 16;
    const uint32_t dA  = smb + (uint32_t)ar * 80 + ahalf * 32;
    const uint32_t dBh = dA + 10240;
    const uint32_t dBl = dA + 20480;

    float acc[2][8][4];
#pragma unroll
    for (int a = 0; a < 2; a++)
#pragma unroll
        for (int b = 0; b < 8; b++)
#pragma unroll
            for (int c = 0; c < 4; c++) acc[a][b][c] = 0.f;

    const uint32_t aFragOff = (uint32_t)(wm + (l & 15)) * 80 + (l >> 4) * 16;
    const int nloc = wn + (l & 7) + ((l >> 4) << 3);
    const uint32_t bFragOff = (uint32_t)nloc * 80 + ((l >> 3) & 1) * 16;

#define G0_STAGE(kc, s) do { \
        uint32_t o = (uint32_t)(s) * G0_BUF; \
        const __half* pA = gA + (kc) * 32; \
        const __half* pH = gWh + (kc) * 32; \
        const __half* pL = gWl + (kc) * 32; \
        cp16(dA + o, pA);        cp16(dA + o + 16, pA + 8); \
        cp16(dBh + o, pH);       cp16(dBh + o + 16, pH + 8); \
        cp16(dBl + o, pL);       cp16(dBl + o + 16, pL + 8); \
        CP_COMMIT(); \
    } while (0)

    G0_STAGE(0, 0);
    G0_STAGE(1, 1);

    for (int kc = 0; kc < NC; ++kc) {
        if (kc < NC - 1) { CP_WAIT(1); } else { CP_WAIT(0); }
        __syncthreads();
        if (kc + 2 < NC) G0_STAGE(kc + 2, (kc + 2) % 3);
        const uint32_t base = smb + (uint32_t)(kc % 3) * G0_BUF;
#pragma unroll
        for (int kk = 0; kk < 2; ++kk) {
            uint32_t a[2][4];
#pragma unroll
            for (int mc = 0; mc < 2; ++mc)
                ldsm4(a[mc], base + aFragOff + mc * 1280 + kk * 32);
            uint32_t bh[4][4];
#pragma unroll
            for (int nc = 0; nc < 4; ++nc)
                ldsm4(bh[nc], base + 10240 + bFragOff + nc * 1280 + kk * 32);
#pragma unroll
            for (int mc = 0; mc < 2; ++mc)
#pragma unroll
                for (int nc = 0; nc < 4; ++nc) {
                    mma16816(acc[mc][nc * 2 + 0], a[mc], bh[nc][0], bh[nc][1]);
                    mma16816(acc[mc][nc * 2 + 1], a[mc], bh[nc][2], bh[nc][3]);
                }
            uint32_t bl[4][4];
#pragma unroll
            for (int nc = 0; nc < 4; ++nc)
                ldsm4(bl[nc], base + 20480 + bFragOff + nc * 1280 + kk * 32);
#pragma unroll
            for (int mc = 0; mc < 2; ++mc)
#pragma unroll
                for (int nc = 0; nc < 4; ++nc) {
                    mma16816(acc[mc][nc * 2 + 0], a[mc], bl[nc][0], bl[nc][1]);
                    mma16816(acc[mc][nc * 2 + 1], a[mc], bl[nc][2], bl[nc][3]);
                }
        }
    }

#pragma unroll
    for (int mc = 0; mc < 2; ++mc) {
        int r0 = m0 + wm + mc * 16 + (l >> 2);
#pragma unroll
        for (int f = 0; f < 8; ++f) {
            int c = n0 + wn + f * 8 + (l & 3) * 2;
            float bs0 = bia[c] + bib[c];
            float bs1 = bia[c + 1] + bib[c + 1];
            *(uint32_t*)&g_inp0[(size_t)r0 * HH + c] =
                pack_h2(acc[mc][f][0] + bs0, acc[mc][f][1] + bs1);
            *(uint32_t*)&g_inp0[(size_t)(r0 + 8) * HH + c] =
                pack_h2(acc[mc][f][2] + bs0, acc[mc][f][3] + bs1);
        }
    }
#undef G0_STAGE
}

// ----------------- FUSED layer0 recurrence + layer1 input projection (R14) -----------
#define F_WHH_H 0
#define F_WHH_L 66048
#define F_WIH   132096
#define F_AREG  198144
#define F_ABUF  3072                       /* k16 chunk: 64 rows x 48B */
#define F_SMEM  230912

__global__ void __launch_bounds__(512, 1) rnn0_fused(
    const float* __restrict__ Whh, const float* __restrict__ Wih,
    const float* __restrict__ bi1, const float* __restrict__ bh1)
{
    extern __shared__ char sm[];
    const uint32_t smb = smem_u32(sm);
    const int tid = threadIdx.x, wid = tid >> 5, l = tid & 31;
    const int g = wid >> 2;            // K-group 0..3: k in [g*256, g*256+256)
    const int w4 = wid & 3;            // warp within group: 2m x 2n
    const int mt = blockIdx.x >> 5;
    const int nt = blockIdx.x & 31;
    const int m0 = mt * 64, n0 = nt * 32;
    const int wm = (w4 >> 1) * 32, wn = (w4 & 1) * 16;

    // --- W_hh preload: fp32 -> fp16 hi/lo [n][k], stride 2064B ---
    for (int i = tid; i < 8192; i += 512) {
        int e = i * 4, n = e >> 10, k = e & 1023;
        float4 wv = *(const float4*)&Whh[(size_t)(n0 + n) * HH + k];
        uint32_t h0, l0, h1, l1;
        split2h(wv.x, wv.y, h0, l0);
        split2h(wv.z, wv.w, h1, l1);
        uint32_t off = (uint32_t)n * 2064 + (uint32_t)k * 2;
        *(uint2*)(sm + F_WHH_H + off) = make_uint2(h0, h1);
        *(uint2*)(sm + F_WHH_L + off) = make_uint2(l0, l1);
    }
    // --- W_ih1 preload: fp32 -> single fp16 [n][k], stride 2064B ---
    for (int i = tid; i < 8192; i += 512) {
        int e = i * 4, n = e >> 10, k = e & 1023;
        float4 wv = *(const float4*)&Wih[(size_t)(n0 + n) * HH + k];
        uint32_t p0 = pack_h2(wv.x, wv.y);
        uint32_t p1 = pack_h2(wv.z, wv.w);
        *(uint2*)(sm + F_WIH + (uint32_t)n * 2064 + (uint32_t)k * 2) = make_uint2(p0, p1);
    }
    __syncthreads();

    const uint32_t aFragOff = (uint32_t)(wm + (l & 15)) * 48 + (uint32_t)(l >> 4) * 16;
    const int nloc = wn + (l & 7) + ((l >> 4) << 3);
    const uint32_t bSel = (uint32_t)((l >> 3) & 1) * 16;
    const uint32_t bOffH = smb + F_WHH_H + (uint32_t)nloc * 2064 + bSel;
    const uint32_t bOffL = smb + F_WHH_L + (uint32_t)nloc * 2064 + bSel;
    const uint32_t bOffI = smb + F_WIH   + (uint32_t)nloc * 2064 + bSel;

    const int gt = tid & 127;
    const int sr = gt >> 1, sq = gt & 1;
    const uint32_t sdstBase = smb + F_AREG + (uint32_t)g * 2 * F_ABUF
                            + (uint32_t)sr * 48 + (uint32_t)sq * 16;
    const int gbar = 1 + g;
    const uint32_t psBase = smb + F_AREG;   // partials: [4][64][32] fp32 = 32KB

    const int erow = tid >> 3;
    const int ecq  = (tid & 7) * 4;
    float pb[4];
#pragma unroll
    for (int j = 0; j < 4; j++)
        pb[j] = __ldg(&bi1[n0 + ecq + j]) + __ldg(&bh1[n0 + ecq + j]);

    unsigned* const bctr = &g_arr[mt * 64];

    for (int t = 0; t <= TT; ++t) {
        const bool hasRec = (t < TT);
        uint2 piu = make_uint2(0u, 0u);
        if (hasRec) {
            const __half* ip = g_inp0 + (size_t)t * BH + (size_t)(m0 + erow) * HH + n0 + ecq;
            piu = __ldg((const uint2*)ip);
        }

        float accr[2][2][4], accp[2][2][4];
        if (t > 0) {
#pragma unroll
            for (int a = 0; a < 2; a++)
#pragma unroll
                for (int b = 0; b < 2; b++)
#pragma unroll
                    for (int c2 = 0; c2 < 4; c2++) { accr[a][b][c2] = 0.f; accp[a][b][c2] = 0.f; }

            const __half* gsrc = g_hist + (size_t)(t - 1) * BH
                               + (size_t)(m0 + sr) * HH + g * 256 + sq * 8;
            cp16(sdstBase, gsrc);
            CP_COMMIT();

            for (int c = 0; c < 16; ++c) {
                CP_WAIT(0);
                BARG(gbar);
                if (c < 15) {
                    cp16(sdstBase + (uint32_t)((c + 1) & 1) * F_ABUF, gsrc + (c + 1) * 16);
                    CP_COMMIT();
                }
                const uint32_t abase = smb + F_AREG + (uint32_t)(g * 2 + (c & 1)) * F_ABUF;
                const uint32_t kb = (uint32_t)(g * 256 + c * 16) * 2;
                uint32_t a0[4], a1[4], bi[4];
                ldsm4(a0, abase + aFragOff);
                ldsm4(a1, abase + aFragOff + 768);
                ldsm4(bi, bOffI + kb);
                if (hasRec) {
                    uint32_t bh[4], bl[4];
                    ldsm4(bh, bOffH + kb);
                    ldsm4(bl, bOffL + kb);
                    mma16816(accr[0][0], a0, bh[0], bh[1]);
                    mma16816(accr[0][1], a0, bh[2], bh[3]);
                    mma16816(accr[1][0], a1, bh[0], bh[1]);
                    mma16816(accr[1][1], a1, bh[2], bh[3]);
                    mma16816(accr[0][0], a0, bl[0], bl[1]);
                    mma16816(accr[0][1], a0, bl[2], bl[3]);
                    mma16816(accr[1][0], a1, bl[0], bl[1]);
                    mma16816(accr[1][1], a1, bl[2], bl[3]);
                }
                mma16816(accp[0][0], a0, bi[0], bi[1]);
                mma16816(accp[0][1], a0, bi[2], bi[3]);
                mma16816(accp[1][0], a1, bi[0], bi[1]);
                mma16816(accp[1][1], a1, bi[2], bi[3]);
            }

            __syncthreads();   // all groups done; A bufs free
            if (hasRec) {
#pragma unroll
                for (int mc = 0; mc < 2; ++mc)
#pragma unroll
                    for (int n8 = 0; n8 < 2; ++n8) {
                        int r = wm + mc * 16 + (l >> 2);
                        int cc = wn + n8 * 8 + (l & 3) * 2;
                        uint32_t pa = psBase + (uint32_t)g * 8192 + (uint32_t)r * 128 + cc * 4;
                        asm volatile("st.shared.v2.f32 [%0], {%1, %2};"
                                     :: "r"(pa), "f"(accr[mc][n8][0]), "f"(accr[mc][n8][1]));
                        asm volatile("st.shared.v2.f32 [%0], {%1, %2};"
                                     :: "r"(pa + 8 * 128), "f"(accr[mc][n8][2]), "f"(accr[mc][n8][3]));
                    }
            }
            __syncthreads();
        }

        // --- rec epilogue: v = tanh(sum partials + inp0[t]); write h0[t]; ARRIVE ---
        unsigned bar_tgt = 0;
        if (hasRec) {
            float v[4];
            {
                const __half2* ph = (const __half2*)&piu;
#pragma unroll
                for (int j = 0; j < 2; j++) {
                    float2 f = __half22float2(ph[j]);
                    v[2 * j] = f.x; v[2 * j + 1] = f.y;
                }
            }
            if (t > 0) {
                const uint32_t pa = psBase + (uint32_t)erow * 128 + ecq * 4;
#pragma unroll
                for (int gg = 0; gg < 4; ++gg) {
                    float4 q;
                    asm volatile("ld.shared.v4.f32 {%0,%1,%2,%3}, [%4];"
                                 : "=f"(q.x), "=f"(q.y), "=f"(q.z), "=f"(q.w)
                                 : "r"(pa + gg * 8192));
                    v[0] += q.x; v[1] += q.y; v[2] += q.z; v[3] += q.w;
                }
            }
#pragma unroll
            for (int j = 0; j < 4; j++) v[j] = tanhf(v[j]);
            uint2 u;
            u.x = pack_h2(v[0], v[1]);
            u.y = pack_h2(v[2], v[3]);
            *(uint2*)&g_hist[(size_t)t * BH + (size_t)(m0 + erow) * HH + n0 + ecq] = u;

            __syncthreads();
            if (tid == 0) {
                __threadfence();
                unsigned a = atomicAdd(bctr, 1u) + 1u;
                bar_tgt = ((a - 1u) / 32u + 1u) * 32u;
            }
        }

        // --- phase B (overlapped with barrier wait): inp1[t-1] = proj + bias ---
        if (t > 0) {
#pragma unroll
            for (int mc = 0; mc < 2; ++mc)
#pragma unroll
                for (int n8 = 0; n8 < 2; ++n8) {
                    int r = wm + mc * 16 + (l >> 2);
                    int cc = wn + n8 * 8 + (l & 3) * 2;
                    uint32_t pa = psBase + (uint32_t)g * 8192 + (uint32_t)r * 128 + cc * 4;
                    asm volatile("st.shared.v2.f32 [%0], {%1, %2};"
                                 :: "r"(pa), "f"(accp[mc][n8][0]), "f"(accp[mc][n8][1]));
                    asm volatile("st.shared.v2.f32 [%0], {%1, %2};"
                                 :: "r"(pa + 8 * 128), "f"(accp[mc][n8][2]), "f"(accp[mc][n8][3]));
                }
            __syncthreads();
            {
                float v[4] = { pb[0], pb[1], pb[2], pb[3] };
                const uint32_t pa = psBase + (uint32_t)erow * 128 + ecq * 4;
#pragma unroll
                for (int gg = 0; gg < 4; ++gg) {
                    float4 q;
                    asm volatile("ld.shared.v4.f32 {%0,%1,%2,%3}, [%4];"
                                 : "=f"(q.x), "=f"(q.y), "=f"(q.z), "=f"(q.w)
                                 : "r"(pa + gg * 8192));
                    v[0] += q.x; v[1] += q.y; v[2] += q.z; v[3] += q.w;
                }
                uint2 u;
                u.x = pack_h2(v[0], v[1]);
                u.y = pack_h2(v[2], v[3]);
                *(uint2*)&g_inp1[(size_t)(t - 1) * BH + (size_t)(m0 + erow) * HH + n0 + ecq] = u;
            }
        }

        // --- wait side of the barrier ---
        if (hasRec) {
            if (tid == 0) {
                while (*((volatile unsigned*)bctr) < bar_tgt) { }
                __threadfence();
            }
            __syncthreads();
        }
    }
}

// ----------------- layer1 recurrence (R14 + arrive/wait split w/ inp1 prefetch) -----
#define RN_WHI 0
#define RN_WLO 66048
#define RN_A   132096
#define RN_ABUF 5120                      /* k32 chunk: 64 rows x 80B */
#define RN_SMEM (RN_A + 12 * RN_ABUF)     /* 193536 */

__global__ void __launch_bounds__(512, 1) rnn1(const float* __restrict__ W)
{
    extern __shared__ char sm[];
    const uint32_t smb = smem_u32(sm);
    const int tid = threadIdx.x, wid = tid >> 5, l = tid & 31;
    const int g = wid >> 2;
    const int w4 = wid & 3;
    const int mt = blockIdx.x >> 5;
    const int nt = blockIdx.x & 31;
    const int m0 = mt * 64, n0 = nt * 32;
    const int wm = (w4 >> 1) * 32, wn = (w4 & 1) * 16;

    for (int i = tid; i < 8192; i += 512) {
        int e = i * 4, n = e >> 10, k = e & 1023;
        float4 w4v = *(const float4*)&W[(size_t)(n0 + n) * HH + k];
        uint32_t h0, l0, h1, l1;
        split2h(w4v.x, w4v.y, h0, l0);
        split2h(w4v.z, w4v.w, h1, l1);
        uint32_t off = (uint32_t)n * 2064 + (uint32_t)k * 2;
        *(uint2*)(sm + RN_WHI + off) = make_uint2(h0, h1);
        *(uint2*)(sm + RN_WLO + off) = make_uint2(l0, l1);
    }
    __syncthreads();

    const uint32_t aFragOff = (uint32_t)(wm + (l & 15)) * 80 + (uint32_t)(l >> 4) * 16;
    const int nloc = wn + (l & 7) + ((l >> 4) << 3);
    const uint32_t bOffH = smb + RN_WHI + (uint32_t)nloc * 2064 + ((l >> 3) & 1) * 16;
    const uint32_t bOffL = bOffH + (RN_WLO - RN_WHI);

    const int gt = tid & 127;
    const int sr = gt >> 1, sq = gt & 1;
    const uint32_t sdstBase = smb + RN_A + (uint32_t)g * 3 * RN_ABUF
                            + (uint32_t)sr * 80 + (uint32_t)sq * 32;
    const int gbar = 1 + g;
    const uint32_t psBase = smb + RN_A;

    const int erow = tid >> 3;
    const int ecq  = (tid & 7) * 4;
    const __half* ipb = g_inp1 + (size_t)(m0 + erow) * HH + n0 + ecq;

    unsigned* const bctr = &g_arr[mt * 64 + 32];   // distinct counter from rnn0's

    // prefetch inp1[0] (written by previous launch -> __ldg safe)
    uint2 piu = __ldg((const uint2*)ipb);

    for (int t = 0; t < TT; ++t) {
        if (t > 0) {
            const __half* hsrc = g_h[1 - (t & 1)];
            const __half* gsrc = hsrc + (size_t)(m0 + sr) * HH + g * 256 + sq * 16;

#define RN_STAGE(c, j) do { \
                const __half* p = gsrc + (c) * 32; \
                uint32_t d = sdstBase + (uint32_t)(j) * RN_ABUF; \
                cp16(d, p); cp16(d + 16, p + 8); \
                CP_COMMIT(); \
            } while (0)

            RN_STAGE(0, 0);
            RN_STAGE(1, 1);

            float acc[2][2][4];
#pragma unroll
            for (int a = 0; a < 2; a++)
#pragma unroll
                for (int b = 0; b < 2; b++)
#pragma unroll
                    for (int c = 0; c < 4; c++) acc[a][b][c] = 0.f;

            for (int c = 0; c < 8; ++c) {
                if (c < 7) { CP_WAIT(1); } else { CP_WAIT(0); }
                BARG(gbar);
                if (c + 2 < 8) RN_STAGE(c + 2, (c + 2) % 3);
                const uint32_t abase = smb + RN_A
                    + (uint32_t)(g * 3 + (c % 3)) * RN_ABUF;
#pragma unroll
                for (int kk = 0; kk < 2; ++kk) {
                    const uint32_t kb = (uint32_t)(g * 256 + c * 32 + kk * 16) * 2;
                    uint32_t a0[4], a1[4], bh[4], bl[4];
                    ldsm4(a0, abase + aFragOff + kk * 32);
                    ldsm4(a1, abase + aFragOff + 1280 + kk * 32);
                    ldsm4(bh, bOffH + kb);
                    ldsm4(bl, bOffL + kb);
                    mma16816(acc[0][0], a0, bh[0], bh[1]);
                    mma16816(acc[0][1], a0, bh[2], bh[3]);
                    mma16816(acc[1][0], a1, bh[0], bh[1]);
                    mma16816(acc[1][1], a1, bh[2], bh[3]);
                    mma16816(acc[0][0], a0, bl[0], bl[1]);
                    mma16816(acc[0][1], a0, bl[2], bl[3]);
                    mma16816(acc[1][0], a1, bl[0], bl[1]);
                    mma16816(acc[1][1], a1, bl[2], bl[3]);
                }
            }
#undef RN_STAGE

            __syncthreads();
#pragma unroll
            for (int mc = 0; mc < 2; ++mc)
#pragma unroll
                for (int n8 = 0; n8 < 2; ++n8) {
                    int r = wm + mc * 16 + (l >> 2);
                    int cc = wn + n8 * 8 + (l & 3) * 2;
                    uint32_t pa = psBase + (uint32_t)g * 8192 + (uint32_t)r * 128 + cc * 4;
                    asm volatile("st.shared.v2.f32 [%0], {%1, %2};"
                                 :: "r"(pa), "f"(acc[mc][n8][0]), "f"(acc[mc][n8][1]));
                    asm volatile("st.shared.v2.f32 [%0], {%1, %2};"
                                 :: "r"(pa + 8 * 128), "f"(acc[mc][n8][2]), "f"(acc[mc][n8][3]));
                }
            __syncthreads();
        }

        {
            float v[4];
            {
                const __half2* ph = (const __half2*)&piu;
#pragma unroll
                for (int j = 0; j < 2; j++) {
                    float2 f = __half22float2(ph[j]);
                    v[2 * j] = f.x; v[2 * j + 1] = f.y;
                }
            }
            if (t > 0) {
                const uint32_t pa = psBase + (uint32_t)erow * 128 + ecq * 4;
#pragma unroll
                for (int gg = 0; gg < 4; ++gg) {
                    float4 q;
                    asm volatile("ld.shared.v4.f32 {%0,%1,%2,%3}, [%4];"
                                 : "=f"(q.x), "=f"(q.y), "=f"(q.z), "=f"(q.w)
                                 : "r"(pa + gg * 8192));
                    v[0] += q.x; v[1] += q.y; v[2] += q.z; v[3] += q.w;
                }
            }
#pragma unroll
            for (int j = 0; j < 4; j++) v[j] = tanhf(v[j]);
            uint2 u;
            u.x = pack_h2(v[0], v[1]);
            u.y = pack_h2(v[2], v[3]);
            *(uint2*)&g_h[t & 1][(size_t)(m0 + erow) * HH + n0 + ecq] = u;
        }

        // --- split barrier: arrive, prefetch next inp1 while waiting ---
        __syncthreads();
        unsigned bar_tgt = 0;
        if (tid == 0) {
            __threadfence();
            unsigned a = atomicAdd(bctr, 1u) + 1u;
            bar_tgt = ((a - 1u) / 32u + 1u) * 32u;
        }
        if (t + 1 < TT) {
            piu = __ldg((const uint2*)(ipb + (size_t)(t + 1) * BH));
        }
        if (tid == 0) {
            while (*((volatile unsigned*)bctr) < bar_tgt) { }
            __threadfence();
        }
        __syncthreads();
    }
}

// ----------------- final FC + ReLU ---------------------------------------------------
__global__ void __launch_bounds__(256) fc_kernel(
    const float* __restrict__ fcW, const float* __restrict__ fcb,
    float* __restrict__ out)
{
    const int b = blockIdx.x;
    const int tid = threadIdx.x;
    const __half* h = &g_h[1][(size_t)b * HH];   // t=255 -> buffer 1
    float s = 0.f;
    for (int i = tid; i < HH; i += 256) s += __half2float(h[i]) * fcW[i];
#pragma unroll
    for (int o = 16; o; o >>= 1) s += __shfl_xor_sync(0xFFFFFFFFu, s, o);
    __shared__ float red[8];
    if ((tid & 31) == 0) red[tid >> 5] = s;
    __syncthreads();
    if (tid == 0) {
        float tot = 0.f;
#pragma unroll
        for (int i = 0; i < 8; i++) tot += red[i];
        out[b] = fmaxf(tot + fcb[0], 0.f);
    }
}

// ----------------- launch ------------------------------------------------------------
extern "C" void kernel_launch(void* const* d_in, const int* in_sizes, int n_in,
                              void* d_out, int out_size)
{
    const float* x     = (const float*)d_in[0];
    const float* W_ih0 = (const float*)d_in[1];
    const float* W_hh0 = (const float*)d_in[2];
    const float* b_ih0 = (const float*)d_in[3];
    const float* b_hh0 = (const float*)d_in[4];
    const float* W_ih1 = (const float*)d_in[5];
    const float* W_hh1 = (const float*)d_in[6];
    const float* b_ih1 = (const float*)d_in[7];
    const float* b_hh1 = (const float*)d_in[8];
    const float* fc_W  = (const float*)d_in[9];
    const float* fc_b  = (const float*)d_in[10];
    float* out = (float*)d_out;

    cudaFuncSetAttribute(gemm0_f16, cudaFuncAttributeMaxDynamicSharedMemorySize, G0_SMEM);
    cudaFuncSetAttribute(rnn0_fused, cudaFuncAttributeMaxDynamicSharedMemorySize, F_SMEM);
    cudaFuncSetAttribute(rnn1, cudaFuncAttributeMaxDynamicSharedMemorySize, RN_SMEM);

    conv_x<<<(TT * BB * II / 4) / 256, 256>>>(x);
    conv_w0<<<(HH * II / 4 + 255) / 256, 256>>>(W_ih0, HH * II / 4);

    dim3 g0grid(HH / 128, (TT * BB) / 128);  // (8, 512)
    gemm0_f16<<<g0grid, 256, G0_SMEM>>>(b_ih0, b_hh0);
    rnn0_fused<<<128, 512, F_SMEM>>>(W_hh0, W_ih1, b_ih1, b_hh1);
    rnn1<<<128, 512, RN_SMEM>>>(W_hh1);
    fc_kernel<<<BB, 256>>>(fc_W, fc_b, out);
}